// round 6
// baseline (speedup 1.0000x reference)
#include <cuda_runtime.h>

// Problem constants
#define BB     8
#define NN     2048
#define DF     256     // d_feat
#define KF     257     // d_feat + 1
#define DH     64      // head dim
#define QKW    128     // q(64) | k(64) packed per row

// ---------------- scratch (__device__ globals; no allocation) ----------------
__device__ float g_QK[(size_t)BB * NN * QKW];          // 8 MB: [row][0..63]=q, [64..127]=k
__device__ float g_cs_part[(size_t)BB * 16 * NN];      // per-(b, n-tile) column-sum partials
__device__ float g_cs[(size_t)BB * NN];                // final column sums
__device__ float g_y_part[(size_t)BB * 16 * NN * 3];   // per-(b, n-chunk) y partials

// =============================================================================
// K1: fc = [f | log_eps] ; QK[row] = fc @ [W_q | W_k]   (16384 x 257 x 128)
// Tile: 64 rows x 128 cols, 256 threads, 4x8 per thread, K-chunks of 32.
// =============================================================================
__global__ __launch_bounds__(256) void k1_proj(
    const float* __restrict__ f, const float* __restrict__ le,
    const float* __restrict__ Wq, const float* __restrict__ Wk)
{
    __shared__ float As[32][68];    // [k][n]  (64 rows + pad)
    __shared__ float Bs[32][132];   // [k][h]  (128 cols + pad)

    const int t  = threadIdx.x;
    const int ty = t >> 4;          // 0..15 -> rows ty*4..ty*4+3
    const int tx = t & 15;          // 0..15 -> cols tx*8..tx*8+7
    const int rowBase = blockIdx.x * 64;      // global row (b*N + n)
    const int b = rowBase / NN;

    float acc[4][8];
    #pragma unroll
    for (int i = 0; i < 4; i++)
        #pragma unroll
        for (int j = 0; j < 8; j++) acc[i][j] = 0.f;

    for (int kc = 0; kc < 9; kc++) {
        const int k0 = kc * 32;
        const int len = (KF - k0 < 32) ? (KF - k0) : 32;   // 32 or 1
        __syncthreads();
        if (len == 32) {
            // As: 64 n x 32 k
            #pragma unroll
            for (int it = 0; it < 2; it++) {
                int n  = (t >> 3) + it * 32;
                int kk = (t & 7) * 4;
                float4 v = *(const float4*)&f[(size_t)(rowBase + n) * DF + k0 + kk];
                As[kk + 0][n] = v.x; As[kk + 1][n] = v.y;
                As[kk + 2][n] = v.z; As[kk + 3][n] = v.w;
            }
            // Bs: 32 k x 128 h
            #pragma unroll
            for (int it = 0; it < 4; it++) {
                int kk = (t >> 5) + it * 8;
                int h  = (t & 31) * 4;
                int c  = k0 + kk;
                float4 v = (h < 64) ? *(const float4*)&Wq[c * DH + h]
                                    : *(const float4*)&Wk[c * DH + (h - 64)];
                Bs[kk][h + 0] = v.x; Bs[kk][h + 1] = v.y;
                Bs[kk][h + 2] = v.z; Bs[kk][h + 3] = v.w;
            }
        } else {
            // last chunk: single fc column = log_eps[b]
            float lv = le[b];
            for (int idx = t; idx < 32 * 64; idx += 256) {
                int kk = idx >> 6, n = idx & 63;
                As[kk][n] = (kk == 0) ? lv : 0.f;
            }
            if (t < 32) {
                int h = t * 4;
                float4 v = (h < 64) ? *(const float4*)&Wq[256 * DH + h]
                                    : *(const float4*)&Wk[256 * DH + (h - 64)];
                Bs[0][h + 0] = v.x; Bs[0][h + 1] = v.y;
                Bs[0][h + 2] = v.z; Bs[0][h + 3] = v.w;
            }
        }
        __syncthreads();
        #pragma unroll 8
        for (int kk = 0; kk < 32; kk++) {
            float4 av = *(const float4*)&As[kk][ty * 4];
            float4 b0 = *(const float4*)&Bs[kk][tx * 8];
            float4 b1 = *(const float4*)&Bs[kk][tx * 8 + 4];
            float a[4]  = {av.x, av.y, av.z, av.w};
            float bv[8] = {b0.x, b0.y, b0.z, b0.w, b1.x, b1.y, b1.z, b1.w};
            #pragma unroll
            for (int i = 0; i < 4; i++)
                #pragma unroll
                for (int j = 0; j < 8; j++) acc[i][j] += a[i] * bv[j];
        }
    }
    #pragma unroll
    for (int i = 0; i < 4; i++) {
        int row = rowBase + ty * 4 + i;
        float4 o0 = {acc[i][0], acc[i][1], acc[i][2], acc[i][3]};
        float4 o1 = {acc[i][4], acc[i][5], acc[i][6], acc[i][7]};
        *(float4*)&g_QK[(size_t)row * QKW + tx * 8]     = o0;
        *(float4*)&g_QK[(size_t)row * QKW + tx * 8 + 4] = o1;
    }
}

// =============================================================================
// K2: E[n,m] = exp( q_n . k_m / 8 )  written (unnormalized) into pi output,
//     plus deterministic per-(b, n-tile) column-sum partials.
// Tile: 128 n x 128 m, K=64 in two 32-chunks, 256 threads, 8x8 per thread.
// grid (mt=16, nt=16, b=8)
// =============================================================================
__global__ __launch_bounds__(256) void k2_logits(float* __restrict__ pi)
{
    __shared__ float As[32][132];   // q^T: [k][n]
    __shared__ float Bs[32][132];   // k^T: [k][m]

    const int t  = threadIdx.x;
    const int ty = t >> 4;          // rows ty*8..+7
    const int tx = t & 15;          // cols tx*8..+7
    const int m0 = blockIdx.x * 128;
    const int n0 = blockIdx.y * 128;
    const int b  = blockIdx.z;
    const float* Q = g_QK + (size_t)b * NN * QKW;

    float acc[8][8];
    #pragma unroll
    for (int i = 0; i < 8; i++)
        #pragma unroll
        for (int j = 0; j < 8; j++) acc[i][j] = 0.f;

    for (int kc = 0; kc < 2; kc++) {
        __syncthreads();
        #pragma unroll
        for (int it = 0; it < 4; it++) {
            int r  = (t >> 3) + it * 32;      // 0..127
            int kk = (t & 7) * 4;
            float4 v = *(const float4*)&Q[(size_t)(n0 + r) * QKW + kc * 32 + kk];
            As[kk + 0][r] = v.x; As[kk + 1][r] = v.y;
            As[kk + 2][r] = v.z; As[kk + 3][r] = v.w;
            float4 w = *(const float4*)&Q[(size_t)(m0 + r) * QKW + 64 + kc * 32 + kk];
            Bs[kk + 0][r] = w.x; Bs[kk + 1][r] = w.y;
            Bs[kk + 2][r] = w.z; Bs[kk + 3][r] = w.w;
        }
        __syncthreads();
        #pragma unroll 8
        for (int kk = 0; kk < 32; kk++) {
            float4 a0 = *(const float4*)&As[kk][ty * 8];
            float4 a1 = *(const float4*)&As[kk][ty * 8 + 4];
            float4 c0 = *(const float4*)&Bs[kk][tx * 8];
            float4 c1 = *(const float4*)&Bs[kk][tx * 8 + 4];
            float a[8]  = {a0.x, a0.y, a0.z, a0.w, a1.x, a1.y, a1.z, a1.w};
            float bv[8] = {c0.x, c0.y, c0.z, c0.w, c1.x, c1.y, c1.z, c1.w};
            #pragma unroll
            for (int i = 0; i < 8; i++)
                #pragma unroll
                for (int j = 0; j < 8; j++) acc[i][j] += a[i] * bv[j];
        }
    }

    // exp + store + per-thread column sums
    float csj[8];
    #pragma unroll
    for (int j = 0; j < 8; j++) csj[j] = 0.f;
    const size_t piBase = (size_t)b * NN * NN;
    #pragma unroll
    for (int i = 0; i < 8; i++) {
        int n = n0 + ty * 8 + i;
        float ev[8];
        #pragma unroll
        for (int j = 0; j < 8; j++) {
            ev[j] = __expf(acc[i][j] * 0.125f);
            csj[j] += ev[j];
        }
        float4 o0 = {ev[0], ev[1], ev[2], ev[3]};
        float4 o1 = {ev[4], ev[5], ev[6], ev[7]};
        *(float4*)&pi[piBase + (size_t)n * NN + m0 + tx * 8]     = o0;
        *(float4*)&pi[piBase + (size_t)n * NN + m0 + tx * 8 + 4] = o1;
    }

    // reduce column sums across the 16 ty rows (deterministic, no atomics)
    __syncthreads();
    float* red = &As[0][0];   // 16*128 floats fit in As
    #pragma unroll
    for (int j = 0; j < 8; j++) red[ty * 128 + tx * 8 + j] = csj[j];
    __syncthreads();
    if (t < 128) {
        float s = 0.f;
        #pragma unroll
        for (int r = 0; r < 16; r++) s += red[r * 128 + t];
        g_cs_part[(size_t)(b * 16 + blockIdx.y) * NN + m0 + t] = s;
    }
}

// K2b: colsum[b][m] = sum over 16 n-tiles
__global__ void k2b_reduce()
{
    int i = blockIdx.x * 256 + threadIdx.x;      // 0 .. B*N-1
    int b = i >> 11, m = i & (NN - 1);
    float s = 0.f;
    #pragma unroll
    for (int nt = 0; nt < 16; nt++) s += g_cs_part[(size_t)(b * 16 + nt) * NN + m];
    g_cs[i] = s;
}

// =============================================================================
// K3: normalize pi in place (pi = e/colsum/N) and accumulate y partials
//     y[b,m,d] = sum_n (e/colsum) * x[n,d].  grid (mt=8, nc=16, b=8), 256 thr.
// =============================================================================
__global__ __launch_bounds__(256) void k3_norm(
    const float* __restrict__ x, float* __restrict__ pi)
{
    const int t  = threadIdx.x;
    const int m  = blockIdx.x * 256 + t;
    const int nc = blockIdx.y;
    const int b  = blockIdx.z;
    const float inv  = 1.0f / g_cs[(size_t)b * NN + m];
    const float invN = 1.0f / (float)NN;

    float a0 = 0.f, a1 = 0.f, a2 = 0.f;
    size_t base = (size_t)b * NN * NN + (size_t)(nc * 128) * NN + m;
    const float* xb = x + (size_t)b * NN * 3 + (size_t)(nc * 128) * 3;
    #pragma unroll 4
    for (int n = 0; n < 128; n++) {
        float e = pi[base + (size_t)n * NN];
        float p = e * inv;
        pi[base + (size_t)n * NN] = p * invN;
        float x0 = xb[n * 3 + 0], x1 = xb[n * 3 + 1], x2 = xb[n * 3 + 2];
        a0 += p * x0; a1 += p * x1; a2 += p * x2;
    }
    size_t yi = ((size_t)(b * 16 + nc) * NN + m) * 3;
    g_y_part[yi + 0] = a0;
    g_y_part[yi + 1] = a1;
    g_y_part[yi + 2] = a2;
}

// K4: reduce y partials into d_out's y region
__global__ void k4_reduce(float* __restrict__ y)
{
    int i = blockIdx.x * 256 + threadIdx.x;      // 0 .. 49151
    int b = i / (NN * 3);
    int r = i - b * (NN * 3);                    // m*3 + d
    float s = 0.f;
    #pragma unroll
    for (int nc = 0; nc < 16; nc++)
        s += g_y_part[(size_t)(b * 16 + nc) * (NN * 3) + r];
    y[i] = s;
}

// =============================================================================
extern "C" void kernel_launch(void* const* d_in, const int* in_sizes, int n_in,
                              void* d_out, int out_size)
{
    const float* f  = (const float*)d_in[0];   // (B, N, 256)
    const float* x  = (const float*)d_in[1];   // (B, N, 3)
    const float* le = (const float*)d_in[2];   // (B,)
    const float* Wq = (const float*)d_in[3];   // (257, 64)
    const float* Wk = (const float*)d_in[4];   // (257, 64)

    float* out = (float*)d_out;
    float* y   = out;                          // (B, N, 3)  = 49152 floats
    float* pi  = out + (size_t)BB * NN * 3;    // (B, N, N)

    k1_proj<<<(BB * NN) / 64, 256>>>(f, le, Wq, Wk);
    k2_logits<<<dim3(16, 16, BB), 256>>>(pi);
    k2b_reduce<<<(BB * NN) / 256, 256>>>();
    k3_norm<<<dim3(8, 16, BB), 256>>>(x, pi);
    k4_reduce<<<(BB * NN * 3) / 256, 256>>>(y);
}